// round 1
// baseline (speedup 1.0000x reference)
#include <cuda_runtime.h>
#include <cstddef>

// Problem constants
#define BB 8
#define NN 8192
#define CF 64
#define SP 1024        // npoint
#define KS 32          // nsample
#define TOK (BB*SP*KS) // 262144 tokens

// ---------------- scratch (static device globals; no allocation) ----------------
__device__ float g_X0[67 * TOK];    // layer0 input  (channel-major [c][tok])
__device__ float g_Y0[64 * TOK];    // layer0 raw output
__device__ float g_Y1[64 * TOK];    // layer1 raw output
__device__ float g_Y2[128 * TOK];   // layer2 raw output
__device__ int   g_idx[TOK];        // ball query indices
__device__ float g_psum[128 * 32];  // BN partial sums
__device__ float g_psq[128 * 32];   // BN partial sums of squares
__device__ float g_sA[3 * 128];     // per-layer BN scale  (g * rstd)
__device__ float g_sB[3 * 128];     // per-layer BN shift  (beta - mean*g*rstd)

// ---------------- FPS: one block per batch, 1024 threads, 8 pts/thread ----------------
__global__ __launch_bounds__(1024)
void fps_kernel(const float* __restrict__ xyz, float* __restrict__ newxyz) {
    const int b = blockIdx.x;
    const int tid = threadIdx.x;
    const int lane = tid & 31;
    const int wid = tid >> 5;
    const float* bx = xyz + (size_t)b * NN * 3;

    float px[8], py[8], pz[8], dd[8];
#pragma unroll
    for (int i = 0; i < 8; ++i) {
        int p = tid + (i << 10);
        px[i] = bx[p * 3 + 0];
        py[i] = bx[p * 3 + 1];
        pz[i] = bx[p * 3 + 2];
        dd[i] = 1e10f;
    }

    __shared__ float sval[32];
    __shared__ int   sidx[32];
    __shared__ int   scur;

    int cur = 0;
    for (int s = 0; s < SP; ++s) {
        // broadcast centroid read (same address across all threads; L1-resident)
        float cx = bx[cur * 3 + 0];
        float cy = bx[cur * 3 + 1];
        float cz = bx[cur * 3 + 2];
        if (tid == 0) {
            float* o = newxyz + ((size_t)b * SP + s) * 3;
            o[0] = cx; o[1] = cy; o[2] = cz;
        }
        // update min-dist (reference-exact arithmetic) + local argmax
        float best = -1.0f;
        int   bi = 0;
#pragma unroll
        for (int i = 0; i < 8; ++i) {
            float dx = __fsub_rn(px[i], cx);
            float dy = __fsub_rn(py[i], cy);
            float dz = __fsub_rn(pz[i], cz);
            float d = __fadd_rn(__fadd_rn(__fmul_rn(dx, dx), __fmul_rn(dy, dy)),
                                __fmul_rn(dz, dz));
            float nd = fminf(dd[i], d);
            dd[i] = nd;
            if (nd > best) { best = nd; bi = tid + (i << 10); }  // i ascending => index ascending
        }
        // warp argmax (first-index tie-break)
#pragma unroll
        for (int off = 16; off; off >>= 1) {
            float ov = __shfl_xor_sync(0xffffffffu, best, off);
            int   oi = __shfl_xor_sync(0xffffffffu, bi, off);
            if (ov > best || (ov == best && oi < bi)) { best = ov; bi = oi; }
        }
        if (lane == 0) { sval[wid] = best; sidx[wid] = bi; }
        __syncthreads();
        if (wid == 0) {
            best = sval[lane]; bi = sidx[lane];
#pragma unroll
            for (int off = 16; off; off >>= 1) {
                float ov = __shfl_xor_sync(0xffffffffu, best, off);
                int   oi = __shfl_xor_sync(0xffffffffu, bi, off);
                if (ov > best || (ov == best && oi < bi)) { best = ov; bi = oi; }
            }
            if (lane == 0) scur = bi;
        }
        __syncthreads();
        cur = scur;
    }
}

// ---------------- ball query: one warp per centroid, ascending scan w/ early exit ----------------
__global__ __launch_bounds__(256)
void ballquery_kernel(const float* __restrict__ xyz, const float* __restrict__ newxyz) {
    const int lane = threadIdx.x & 31;
    const int wslot = threadIdx.x >> 5;
    const int gw = blockIdx.x * 8 + wslot;   // 0..8191
    const int b = gw >> 10;
    __shared__ int sbuf[8][32];

    const float* bx = xyz + (size_t)b * NN * 3;
    const float* cp = newxyz + (size_t)gw * 3;
    const float cx = cp[0], cy = cp[1], cz = cp[2];
    const float R2 = (float)(0.2 * 0.2);   // matches JAX weak-typed double->f32 constant

    int cnt = 0;
    for (int base = 0; base < NN && cnt < KS; base += 32) {
        int p = base + lane;
        float dx = __fsub_rn(bx[p * 3 + 0], cx);
        float dy = __fsub_rn(bx[p * 3 + 1], cy);
        float dz = __fsub_rn(bx[p * 3 + 2], cz);
        float d = __fadd_rn(__fadd_rn(__fmul_rn(dx, dx), __fmul_rn(dy, dy)),
                            __fmul_rn(dz, dz));
        bool in = (d <= R2);   // reference excludes d > r^2
        unsigned m = __ballot_sync(0xffffffffu, in);
        int pos = cnt + __popc(m & ((1u << lane) - 1u));
        if (in && pos < KS) sbuf[wslot][pos] = p;
        cnt += __popc(m);
    }
    __syncwarp();
    int cfin = cnt < KS ? cnt : KS;
    int v = sbuf[wslot][lane < cfin ? lane : 0];  // pad with first index
    g_idx[(size_t)gw * KS + lane] = v;
}

// ---------------- gather + concat into channel-major X0 ----------------
__global__ __launch_bounds__(256)
void gather_kernel(const float* __restrict__ xyz, const float* __restrict__ feat,
                   const float* __restrict__ newxyz) {
    int tok = blockIdx.x * 256 + threadIdx.x;   // 262144 total
    int b = tok >> 15;
    int s = (tok >> 5) & 1023;
    int n = g_idx[tok];
    const float* p = xyz + ((size_t)b * NN + n) * 3;
    const float* c = newxyz + ((size_t)b * SP + s) * 3;
    g_X0[0 * TOK + tok] = p[0] - c[0];
    g_X0[1 * TOK + tok] = p[1] - c[1];
    g_X0[2 * TOK + tok] = p[2] - c[2];
    const float* fb = feat + (size_t)b * CF * NN + n;
#pragma unroll 8
    for (int cc = 0; cc < CF; ++cc)
        g_X0[(3 + cc) * TOK + tok] = fb[(size_t)cc * NN];
}

// ---------------- 1x1-conv GEMM: 64-out tile, 1 token/thread, W broadcast from smem ----------------
template <int CIN, bool BN>
__global__ __launch_bounds__(256)
void mlp_gemm(const float* __restrict__ X, const float* __restrict__ W,
              const float* __restrict__ bias,
              const float* __restrict__ sA, const float* __restrict__ sB,
              float* __restrict__ Y) {
    const int o_base = blockIdx.y * 64;
    __shared__ float Wt[CIN * 64];     // [c][o]
    __shared__ float sbias[64];
    __shared__ float shA[CIN], shB[CIN];

    for (int i = threadIdx.x; i < CIN * 64; i += 256) {
        int c = i >> 6, o = i & 63;
        Wt[c * 64 + o] = W[(size_t)(o_base + o) * CIN + c];
    }
    if (threadIdx.x < 64) sbias[threadIdx.x] = bias[o_base + threadIdx.x];
    if (BN) {
        for (int i = threadIdx.x; i < CIN; i += 256) { shA[i] = sA[i]; shB[i] = sB[i]; }
    }
    __syncthreads();

    const int tok = blockIdx.x * 256 + threadIdx.x;
    float acc[64];
#pragma unroll
    for (int o = 0; o < 64; ++o) acc[o] = 0.0f;

    const float4* Wt4 = (const float4*)Wt;
#pragma unroll 2
    for (int c = 0; c < CIN; ++c) {
        float xv = X[(size_t)c * TOK + tok];
        if (BN) xv = fmaxf(0.0f, fmaf(xv, shA[c], shB[c]));  // relu(bn(prev)) on load
#pragma unroll
        for (int j = 0; j < 16; ++j) {
            float4 w = Wt4[c * 16 + j];
            acc[4 * j + 0] = fmaf(w.x, xv, acc[4 * j + 0]);
            acc[4 * j + 1] = fmaf(w.y, xv, acc[4 * j + 1]);
            acc[4 * j + 2] = fmaf(w.z, xv, acc[4 * j + 2]);
            acc[4 * j + 3] = fmaf(w.w, xv, acc[4 * j + 3]);
        }
    }
#pragma unroll
    for (int o = 0; o < 64; ++o)
        Y[(size_t)(o_base + o) * TOK + tok] = acc[o] + sbias[o];
}

// ---------------- BN stats: deterministic two-stage reduction ----------------
__global__ __launch_bounds__(256)
void stats_partial(const float* __restrict__ Y) {
    const int o = blockIdx.x, chunk = blockIdx.y;
    const float* p = Y + (size_t)o * TOK + (size_t)chunk * 8192;
    float s = 0.0f, s2 = 0.0f;
    for (int i = threadIdx.x; i < 8192; i += 256) {
        float v = p[i];
        s += v;
        s2 = fmaf(v, v, s2);
    }
    __shared__ float rs[256], rq[256];
    rs[threadIdx.x] = s; rq[threadIdx.x] = s2;
    __syncthreads();
    for (int st = 128; st; st >>= 1) {
        if (threadIdx.x < st) {
            rs[threadIdx.x] += rs[threadIdx.x + st];
            rq[threadIdx.x] += rq[threadIdx.x + st];
        }
        __syncthreads();
    }
    if (threadIdx.x == 0) {
        g_psum[o * 32 + chunk] = rs[0];
        g_psq[o * 32 + chunk] = rq[0];
    }
}

__global__ void stats_final(const float* __restrict__ g, const float* __restrict__ beta,
                            int cout, int layer) {
    int o = threadIdx.x;
    if (o < cout) {
        float s = 0.0f, q = 0.0f;
        for (int c = 0; c < 32; ++c) { s += g_psum[o * 32 + c]; q += g_psq[o * 32 + c]; }
        const float inv = 1.0f / (float)TOK;
        float mean = s * inv;
        float var = q * inv - mean * mean;
        float rstd = rsqrtf(var + 1e-5f);
        float a = g[o] * rstd;
        g_sA[layer * 128 + o] = a;
        g_sB[layer * 128 + o] = fmaf(-mean, a, beta[o]);
    }
}

// ---------------- final: bn+relu+max over nsample ----------------
__global__ __launch_bounds__(256)
void maxpool_kernel(float* __restrict__ out) {
    int idx = blockIdx.x * 256 + threadIdx.x;   // 0..1048575 : ((b*128+o)*1024+s)
    int b = idx >> 17;
    int o = (idx >> 10) & 127;
    int s = idx & 1023;
    const float a = g_sA[256 + o];
    const float sh = g_sB[256 + o];
    const float4* p = (const float4*)(g_Y2 + (size_t)o * TOK + ((size_t)b << 15) + ((size_t)s << 5));
    float m = 0.0f;   // relu floor; max_k relu(z) == max(max_k bn(z), 0)
#pragma unroll
    for (int j = 0; j < 8; ++j) {
        float4 v = p[j];
        m = fmaxf(m, fmaf(v.x, a, sh));
        m = fmaxf(m, fmaf(v.y, a, sh));
        m = fmaxf(m, fmaf(v.z, a, sh));
        m = fmaxf(m, fmaf(v.w, a, sh));
    }
    out[24576 + idx] = m;
}

// ---------------- launcher ----------------
extern "C" void kernel_launch(void* const* d_in, const int* in_sizes, int n_in,
                              void* d_out, int out_size) {
    const float* xyz  = (const float*)d_in[0];
    const float* feat = (const float*)d_in[1];
    const float* W0 = (const float*)d_in[2];
    const float* b0 = (const float*)d_in[3];
    const float* g0 = (const float*)d_in[4];
    const float* be0 = (const float*)d_in[5];
    const float* W1 = (const float*)d_in[6];
    const float* b1 = (const float*)d_in[7];
    const float* g1 = (const float*)d_in[8];
    const float* be1 = (const float*)d_in[9];
    const float* W2 = (const float*)d_in[10];
    const float* b2 = (const float*)d_in[11];
    const float* g2 = (const float*)d_in[12];
    const float* be2 = (const float*)d_in[13];

    float* out = (float*)d_out;
    float* newxyz = out;   // first 8*1024*3 elements

    float *X0, *Y0, *Y1, *Y2, *sA, *sB;
    cudaGetSymbolAddress((void**)&X0, g_X0);
    cudaGetSymbolAddress((void**)&Y0, g_Y0);
    cudaGetSymbolAddress((void**)&Y1, g_Y1);
    cudaGetSymbolAddress((void**)&Y2, g_Y2);
    cudaGetSymbolAddress((void**)&sA, g_sA);
    cudaGetSymbolAddress((void**)&sB, g_sB);

    fps_kernel<<<BB, 1024>>>(xyz, newxyz);
    ballquery_kernel<<<1024, 256>>>(xyz, newxyz);
    gather_kernel<<<TOK / 256, 256>>>(xyz, feat, newxyz);

    // layer 0: 67 -> 64
    mlp_gemm<67, false><<<dim3(TOK / 256, 1), 256>>>(X0, W0, b0, nullptr, nullptr, Y0);
    stats_partial<<<dim3(64, 32), 256>>>(Y0);
    stats_final<<<1, 128>>>(g0, be0, 64, 0);

    // layer 1: 64 -> 64 (applies bn+relu of layer0 on load)
    mlp_gemm<64, true><<<dim3(TOK / 256, 1), 256>>>(Y0, W1, b1, sA + 0, sB + 0, Y1);
    stats_partial<<<dim3(64, 32), 256>>>(Y1);
    stats_final<<<1, 128>>>(g1, be1, 64, 1);

    // layer 2: 64 -> 128 (two 64-wide output tiles)
    mlp_gemm<64, true><<<dim3(TOK / 256, 2), 256>>>(Y1, W2, b2, sA + 128, sB + 128, Y2);
    stats_partial<<<dim3(128, 32), 256>>>(Y2);
    stats_final<<<1, 128>>>(g2, be2, 128, 2);

    maxpool_kernel<<<(BB * 128 * SP) / 256, 256>>>(out);
}

// round 2
// speedup vs baseline: 1.8781x; 1.8781x over previous
#include <cuda_runtime.h>
#include <cstddef>

// Problem constants
#define BB 8
#define NN 8192
#define CF 64
#define SP 1024        // npoint
#define KS 32          // nsample
#define TOK (BB*SP*KS) // 262144 tokens

// ---------------- scratch (static device globals; no allocation) ----------------
__device__ float g_X0[67 * TOK];    // layer0 input  (channel-major [c][tok])
__device__ float g_Y0[64 * TOK];    // layer0 raw output
__device__ float g_Y1[64 * TOK];    // layer1 raw output
__device__ float g_Y2[128 * TOK];   // layer2 raw output
__device__ int   g_idx[TOK];        // ball query indices
__device__ float g_psum[128 * 32];  // BN partial sums
__device__ float g_psq[128 * 32];   // BN partial sums of squares
__device__ float g_sA[3 * 128];     // per-layer BN scale  (g * rstd)
__device__ float g_sB[3 * 128];     // per-layer BN shift  (beta - mean*g*rstd)

// ---------------- f32x2 packed helpers (exact .rn per lane) ----------------
__device__ __forceinline__ unsigned long long pack2(float lo, float hi) {
    unsigned long long r;
    asm("mov.b64 %0, {%1, %2};" : "=l"(r) : "r"(__float_as_uint(lo)), "r"(__float_as_uint(hi)));
    return r;
}
__device__ __forceinline__ void unpack2(unsigned long long v, float& lo, float& hi) {
    unsigned a, b;
    asm("mov.b64 {%0, %1}, %2;" : "=r"(a), "=r"(b) : "l"(v));
    lo = __uint_as_float(a); hi = __uint_as_float(b);
}
__device__ __forceinline__ unsigned long long add2(unsigned long long a, unsigned long long b) {
    unsigned long long r;
    asm("add.rn.f32x2 %0, %1, %2;" : "=l"(r) : "l"(a), "l"(b));
    return r;
}
__device__ __forceinline__ unsigned long long mul2(unsigned long long a, unsigned long long b) {
    unsigned long long r;
    asm("mul.rn.f32x2 %0, %1, %2;" : "=l"(r) : "l"(a), "l"(b));
    return r;
}

// ---------------- FPS: one block per batch, 512 threads, 16 pts/thread (8 packed pairs) ----------------
#define FPS_T 512
#define FPS_W (FPS_T / 32)
__global__ __launch_bounds__(FPS_T)
void fps_kernel(const float* __restrict__ xyz, float* __restrict__ newxyz) {
    const int b = blockIdx.x;
    const int tid = threadIdx.x;
    const int lane = tid & 31;
    const int wid = tid >> 5;
    const float* bx = xyz + (size_t)b * NN * 3;

    // thread owns points [tid*16, tid*16+16), packed in 8 (even,odd) pairs
    const int base = tid * 16;
    unsigned long long px2[8], py2[8], pz2[8];
    float dl[8], dh[8];
#pragma unroll
    for (int j = 0; j < 8; ++j) {
        int p = base + 2 * j;
        px2[j] = pack2(bx[p * 3 + 0], bx[p * 3 + 3]);
        py2[j] = pack2(bx[p * 3 + 1], bx[p * 3 + 4]);
        pz2[j] = pack2(bx[p * 3 + 2], bx[p * 3 + 5]);
        dl[j] = 1e10f; dh[j] = 1e10f;
    }

    __shared__ unsigned smax[2][FPS_W];
    __shared__ unsigned sarg[2][FPS_W];

    int cur = 0;
    for (int s = 0; s < SP; ++s) {
        // broadcast centroid (uniform address; L1-resident)
        float cx = bx[cur * 3 + 0];
        float cy = bx[cur * 3 + 1];
        float cz = bx[cur * 3 + 2];
        if (tid == 0) {
            float* o = newxyz + ((size_t)b * SP + s) * 3;
            o[0] = cx; o[1] = cy; o[2] = cz;
        }
        unsigned long long cxx = pack2(-cx, -cx);
        unsigned long long cyy = pack2(-cy, -cy);
        unsigned long long czz = pack2(-cz, -cz);

        float best = 0.0f;          // distances are >= 0
        int   bi = 0x3FFFFFFF;      // sentinel: loses min-index tie-break
#pragma unroll
        for (int j = 0; j < 8; ++j) {
            // p - c == p + (-c) exactly; (dx^2 + dy^2) + dz^2 association matches ref
            unsigned long long dx = add2(px2[j], cxx);
            unsigned long long dy = add2(py2[j], cyy);
            unsigned long long dz = add2(pz2[j], czz);
            unsigned long long d2 = add2(add2(mul2(dx, dx), mul2(dy, dy)), mul2(dz, dz));
            float d0, d1;
            unpack2(d2, d0, d1);
            float n0 = fminf(dl[j], d0); dl[j] = n0;
            float n1 = fminf(dh[j], d1); dh[j] = n1;
            if (n0 > best) { best = n0; bi = base + 2 * j; }     // ascending index order
            if (n1 > best) { best = n1; bi = base + 2 * j + 1; } // => first-max tie-break
        }
        // warp argmax via single-instruction redux (values are non-negative floats)
        unsigned vb = __float_as_uint(best);
        unsigned m  = __reduce_max_sync(0xffffffffu, vb);
        unsigned mi = __reduce_min_sync(0xffffffffu, (vb == m) ? (unsigned)bi : 0xFFFFFFFFu);

        const int pb = s & 1;  // parity double-buffer => single barrier per step
        if (lane == 0) { smax[pb][wid] = m; sarg[pb][wid] = mi; }
        __syncthreads();
        // every warp redundantly reduces the 16 partials (no second barrier / broadcast)
        unsigned v = (lane < FPS_W) ? smax[pb][lane] : 0u;
        unsigned a = (lane < FPS_W) ? sarg[pb][lane] : 0xFFFFFFFFu;
        unsigned M = __reduce_max_sync(0xffffffffu, v);
        unsigned A = __reduce_min_sync(0xffffffffu, (v == M) ? a : 0xFFFFFFFFu);
        cur = (int)A;
    }
}

// ---------------- ball query: one warp per centroid, ascending scan w/ early exit ----------------
__global__ __launch_bounds__(256)
void ballquery_kernel(const float* __restrict__ xyz, const float* __restrict__ newxyz) {
    const int lane = threadIdx.x & 31;
    const int wslot = threadIdx.x >> 5;
    const int gw = blockIdx.x * 8 + wslot;   // 0..8191
    const int b = gw >> 10;
    __shared__ int sbuf[8][32];

    const float* bx = xyz + (size_t)b * NN * 3;
    const float* cp = newxyz + (size_t)gw * 3;
    const float cx = cp[0], cy = cp[1], cz = cp[2];
    const float R2 = (float)(0.2 * 0.2);

    int cnt = 0;
    for (int base = 0; base < NN && cnt < KS; base += 32) {
        int p = base + lane;
        float dx = __fsub_rn(bx[p * 3 + 0], cx);
        float dy = __fsub_rn(bx[p * 3 + 1], cy);
        float dz = __fsub_rn(bx[p * 3 + 2], cz);
        float d = __fadd_rn(__fadd_rn(__fmul_rn(dx, dx), __fmul_rn(dy, dy)),
                            __fmul_rn(dz, dz));
        bool in = (d <= R2);
        unsigned m = __ballot_sync(0xffffffffu, in);
        int pos = cnt + __popc(m & ((1u << lane) - 1u));
        if (in && pos < KS) sbuf[wslot][pos] = p;
        cnt += __popc(m);
    }
    __syncwarp();
    int cfin = cnt < KS ? cnt : KS;
    int v = sbuf[wslot][lane < cfin ? lane : 0];
    g_idx[(size_t)gw * KS + lane] = v;
}

// ---------------- gather + concat into channel-major X0 ----------------
__global__ __launch_bounds__(256)
void gather_kernel(const float* __restrict__ xyz, const float* __restrict__ feat,
                   const float* __restrict__ newxyz) {
    int tok = blockIdx.x * 256 + threadIdx.x;
    int b = tok >> 15;
    int s = (tok >> 5) & 1023;
    int n = g_idx[tok];
    const float* p = xyz + ((size_t)b * NN + n) * 3;
    const float* c = newxyz + ((size_t)b * SP + s) * 3;
    g_X0[0 * TOK + tok] = p[0] - c[0];
    g_X0[1 * TOK + tok] = p[1] - c[1];
    g_X0[2 * TOK + tok] = p[2] - c[2];
    const float* fb = feat + (size_t)b * CF * NN + n;
#pragma unroll 8
    for (int cc = 0; cc < CF; ++cc)
        g_X0[(3 + cc) * TOK + tok] = fb[(size_t)cc * NN];
}

// ---------------- 1x1-conv GEMM: 32-out x 2-token register tile ----------------
template <int CIN, bool BN>
__global__ __launch_bounds__(256)
void mlp_gemm(const float* __restrict__ X, const float* __restrict__ W,
              const float* __restrict__ bias,
              const float* __restrict__ sA, const float* __restrict__ sB,
              float* __restrict__ Y) {
    const int o_base = blockIdx.y * 32;
    __shared__ float Wt[CIN * 32];     // [c][o]
    __shared__ float sbias[32];
    __shared__ float shA[CIN], shB[CIN];

    for (int i = threadIdx.x; i < CIN * 32; i += 256) {
        int c = i >> 5, o = i & 31;
        Wt[c * 32 + o] = W[(size_t)(o_base + o) * CIN + c];
    }
    if (threadIdx.x < 32) sbias[threadIdx.x] = bias[o_base + threadIdx.x];
    if (BN) {
        for (int i = threadIdx.x; i < CIN; i += 256) { shA[i] = sA[i]; shB[i] = sB[i]; }
    }
    __syncthreads();

    const int tok0 = blockIdx.x * 512 + threadIdx.x;
    const int tok1 = tok0 + 256;
    float a0[32], a1[32];
#pragma unroll
    for (int o = 0; o < 32; ++o) { a0[o] = 0.0f; a1[o] = 0.0f; }

    const float4* Wt4 = (const float4*)Wt;
#pragma unroll 4
    for (int c = 0; c < CIN; ++c) {
        float x0 = X[(size_t)c * TOK + tok0];
        float x1 = X[(size_t)c * TOK + tok1];
        if (BN) {
            float A = shA[c], Bv = shB[c];
            x0 = fmaxf(0.0f, fmaf(x0, A, Bv));
            x1 = fmaxf(0.0f, fmaf(x1, A, Bv));
        }
#pragma unroll
        for (int j = 0; j < 8; ++j) {
            float4 w = Wt4[c * 8 + j];
            a0[4*j+0] = fmaf(w.x, x0, a0[4*j+0]);  a1[4*j+0] = fmaf(w.x, x1, a1[4*j+0]);
            a0[4*j+1] = fmaf(w.y, x0, a0[4*j+1]);  a1[4*j+1] = fmaf(w.y, x1, a1[4*j+1]);
            a0[4*j+2] = fmaf(w.z, x0, a0[4*j+2]);  a1[4*j+2] = fmaf(w.z, x1, a1[4*j+2]);
            a0[4*j+3] = fmaf(w.w, x0, a0[4*j+3]);  a1[4*j+3] = fmaf(w.w, x1, a1[4*j+3]);
        }
    }
#pragma unroll
    for (int o = 0; o < 32; ++o) {
        float bb = sbias[o];
        Y[(size_t)(o_base + o) * TOK + tok0] = a0[o] + bb;
        Y[(size_t)(o_base + o) * TOK + tok1] = a1[o] + bb;
    }
}

// ---------------- BN stats: deterministic two-stage reduction ----------------
__global__ __launch_bounds__(256)
void stats_partial(const float* __restrict__ Y) {
    const int o = blockIdx.x, chunk = blockIdx.y;
    const float* p = Y + (size_t)o * TOK + (size_t)chunk * 8192;
    float s = 0.0f, s2 = 0.0f;
    for (int i = threadIdx.x; i < 8192; i += 256) {
        float v = p[i];
        s += v;
        s2 = fmaf(v, v, s2);
    }
    __shared__ float rs[256], rq[256];
    rs[threadIdx.x] = s; rq[threadIdx.x] = s2;
    __syncthreads();
    for (int st = 128; st; st >>= 1) {
        if (threadIdx.x < st) {
            rs[threadIdx.x] += rs[threadIdx.x + st];
            rq[threadIdx.x] += rq[threadIdx.x + st];
        }
        __syncthreads();
    }
    if (threadIdx.x == 0) {
        g_psum[o * 32 + chunk] = rs[0];
        g_psq[o * 32 + chunk] = rq[0];
    }
}

__global__ void stats_final(const float* __restrict__ g, const float* __restrict__ beta,
                            int cout, int layer) {
    int o = threadIdx.x;
    if (o < cout) {
        float s = 0.0f, q = 0.0f;
        for (int c = 0; c < 32; ++c) { s += g_psum[o * 32 + c]; q += g_psq[o * 32 + c]; }
        const float inv = 1.0f / (float)TOK;
        float mean = s * inv;
        float var = q * inv - mean * mean;
        float rstd = rsqrtf(var + 1e-5f);
        float a = g[o] * rstd;
        g_sA[layer * 128 + o] = a;
        g_sB[layer * 128 + o] = fmaf(-mean, a, beta[o]);
    }
}

// ---------------- final: bn+relu+max over nsample ----------------
__global__ __launch_bounds__(256)
void maxpool_kernel(float* __restrict__ out) {
    int idx = blockIdx.x * 256 + threadIdx.x;   // ((b*128+o)*1024+s)
    int b = idx >> 17;
    int o = (idx >> 10) & 127;
    int s = idx & 1023;
    const float a = g_sA[256 + o];
    const float sh = g_sB[256 + o];
    const float4* p = (const float4*)(g_Y2 + (size_t)o * TOK + ((size_t)b << 15) + ((size_t)s << 5));
    float m = 0.0f;   // relu floor
#pragma unroll
    for (int j = 0; j < 8; ++j) {
        float4 v = p[j];
        m = fmaxf(m, fmaf(v.x, a, sh));
        m = fmaxf(m, fmaf(v.y, a, sh));
        m = fmaxf(m, fmaf(v.z, a, sh));
        m = fmaxf(m, fmaf(v.w, a, sh));
    }
    out[24576 + idx] = m;
}

// ---------------- launcher ----------------
extern "C" void kernel_launch(void* const* d_in, const int* in_sizes, int n_in,
                              void* d_out, int out_size) {
    const float* xyz  = (const float*)d_in[0];
    const float* feat = (const float*)d_in[1];
    const float* W0 = (const float*)d_in[2];
    const float* b0 = (const float*)d_in[3];
    const float* g0 = (const float*)d_in[4];
    const float* be0 = (const float*)d_in[5];
    const float* W1 = (const float*)d_in[6];
    const float* b1 = (const float*)d_in[7];
    const float* g1 = (const float*)d_in[8];
    const float* be1 = (const float*)d_in[9];
    const float* W2 = (const float*)d_in[10];
    const float* b2 = (const float*)d_in[11];
    const float* g2 = (const float*)d_in[12];
    const float* be2 = (const float*)d_in[13];

    float* out = (float*)d_out;
    float* newxyz = out;   // first 8*1024*3 elements

    float *X0, *Y0, *Y1, *Y2, *sA, *sB;
    cudaGetSymbolAddress((void**)&X0, g_X0);
    cudaGetSymbolAddress((void**)&Y0, g_Y0);
    cudaGetSymbolAddress((void**)&Y1, g_Y1);
    cudaGetSymbolAddress((void**)&Y2, g_Y2);
    cudaGetSymbolAddress((void**)&sA, g_sA);
    cudaGetSymbolAddress((void**)&sB, g_sB);

    fps_kernel<<<BB, FPS_T>>>(xyz, newxyz);
    ballquery_kernel<<<1024, 256>>>(xyz, newxyz);
    gather_kernel<<<TOK / 256, 256>>>(xyz, feat, newxyz);

    // layer 0: 67 -> 64
    mlp_gemm<67, false><<<dim3(TOK / 512, 2), 256>>>(X0, W0, b0, nullptr, nullptr, Y0);
    stats_partial<<<dim3(64, 32), 256>>>(Y0);
    stats_final<<<1, 128>>>(g0, be0, 64, 0);

    // layer 1: 64 -> 64 (applies bn+relu of layer0 on load)
    mlp_gemm<64, true><<<dim3(TOK / 512, 2), 256>>>(Y0, W1, b1, sA + 0, sB + 0, Y1);
    stats_partial<<<dim3(64, 32), 256>>>(Y1);
    stats_final<<<1, 128>>>(g1, be1, 64, 1);

    // layer 2: 64 -> 128
    mlp_gemm<64, true><<<dim3(TOK / 512, 4), 256>>>(Y1, W2, b2, sA + 128, sB + 128, Y2);
    stats_partial<<<dim3(128, 32), 256>>>(Y2);
    stats_final<<<1, 128>>>(g2, be2, 128, 2);

    maxpool_kernel<<<(BB * 128 * SP) / 256, 256>>>(out);
}